// round 1
// baseline (speedup 1.0000x reference)
#include <cuda_runtime.h>
#include <math.h>

#define BATCH 16
#define CH    256
#define NPIX  4096            // H*W = 64*64
#define CN    (CH * NPIX)     // per-batch elements
#define BK    32

// Scratch (device globals: allocation-free per harness rules)
__device__ float g_inv1[BATCH * CH];
__device__ float g_inv2[BATCH * CH];
__device__ float g_S1[BATCH * CH * CH];   // 4 MiB: gram sums, then softmax A1 in place
__device__ float g_S2[BATCH * CH * CH];   // 4 MiB

// ---------------------------------------------------------------------------
// Kernel 1: per-row inverse L2 norms over N=4096 for both inputs.
// grid = B*C blocks, 256 threads.
// ---------------------------------------------------------------------------
__global__ __launch_bounds__(256) void norms_kernel(const float* __restrict__ x1,
                                                    const float* __restrict__ x2) {
    const int row = blockIdx.x;                     // b*C + c
    const float4* p1 = (const float4*)(x1 + (size_t)row * NPIX);
    const float4* p2 = (const float4*)(x2 + (size_t)row * NPIX);
    float s1 = 0.f, s2 = 0.f;
    for (int i = threadIdx.x; i < NPIX / 4; i += 256) {
        float4 a = p1[i];
        s1 += a.x * a.x + a.y * a.y + a.z * a.z + a.w * a.w;
        float4 b = p2[i];
        s2 += b.x * b.x + b.y * b.y + b.z * b.z + b.w * b.w;
    }
    __shared__ float sh1[8], sh2[8];
    const int lane = threadIdx.x & 31, w = threadIdx.x >> 5;
    #pragma unroll
    for (int o = 16; o; o >>= 1) {
        s1 += __shfl_xor_sync(0xffffffffu, s1, o);
        s2 += __shfl_xor_sync(0xffffffffu, s2, o);
    }
    if (lane == 0) { sh1[w] = s1; sh2[w] = s2; }
    __syncthreads();
    if (threadIdx.x == 0) {
        float t1 = 0.f, t2 = 0.f;
        #pragma unroll
        for (int i = 0; i < 8; i++) { t1 += sh1[i]; t2 += sh2[i]; }
        g_inv1[row] = 1.f / fmaxf(sqrtf(t1), 1e-12f);
        g_inv2[row] = 1.f / fmaxf(sqrtf(t2), 1e-12f);
    }
}

// ---------------------------------------------------------------------------
// Kernel 2: gram matmuls.
//   s[c,n] = inv1[c]*x1[c,n] + inv2[c]*x2[c,n]
//   S1[c,d] = inv1[d] * sum_n s[c,n]*x1[d,n]
//   S2[c,d] = inv2[d] * sum_n s[c,n]*x2[d,n]
// grid = (4 d-tiles, 4 c-tiles, B), 256 threads, 64x64 tile, 4x4 per thread.
// ---------------------------------------------------------------------------
__global__ __launch_bounds__(256) void gram_kernel(const float* __restrict__ x1,
                                                   const float* __restrict__ x2) {
    __shared__ float s_s [64][BK + 4];   // row-major (c)
    __shared__ float d1_s[BK][68];       // K-major (d contiguous)
    __shared__ float d2_s[BK][68];

    const int b  = blockIdx.z;
    const int c0 = blockIdx.y * 64;
    const int d0 = blockIdx.x * 64;
    const int t  = threadIdx.x;
    const int tx = t & 15, ty = t >> 4;
    const int ty4 = ty * 4, tx4 = tx * 4;

    const float* X1 = x1 + (size_t)b * CN;
    const float* X2 = x2 + (size_t)b * CN;
    const float* inv1 = g_inv1 + b * CH;
    const float* inv2 = g_inv2 + b * CH;

    float acc1[4][4] = {}, acc2[4][4] = {};

    for (int kk = 0; kk < NPIX; kk += BK) {
        #pragma unroll
        for (int u = 0; u < 2; u++) {
            const int v  = t + u * 256;         // 0..511
            const int r  = v >> 3;              // tile row 0..63
            const int kq = (v & 7) * 4;         // k offset (float4)
            // s tile (rows c0+r), fuse the normalization scales
            {
                const int gc = c0 + r;
                const float4 a = *(const float4*)(X1 + (size_t)gc * NPIX + kk + kq);
                const float4 bb = *(const float4*)(X2 + (size_t)gc * NPIX + kk + kq);
                const float i1 = inv1[gc], i2 = inv2[gc];
                float4 s4;
                s4.x = i1 * a.x + i2 * bb.x;
                s4.y = i1 * a.y + i2 * bb.y;
                s4.z = i1 * a.z + i2 * bb.z;
                s4.w = i1 * a.w + i2 * bb.w;
                *(float4*)&s_s[r][kq] = s4;
            }
            // d tiles (rows d0+r), raw, transposed into K-major smem
            {
                const int gd = d0 + r;
                const float4 c4 = *(const float4*)(X1 + (size_t)gd * NPIX + kk + kq);
                const float4 e4 = *(const float4*)(X2 + (size_t)gd * NPIX + kk + kq);
                d1_s[kq + 0][r] = c4.x; d1_s[kq + 1][r] = c4.y;
                d1_s[kq + 2][r] = c4.z; d1_s[kq + 3][r] = c4.w;
                d2_s[kq + 0][r] = e4.x; d2_s[kq + 1][r] = e4.y;
                d2_s[kq + 2][r] = e4.z; d2_s[kq + 3][r] = e4.w;
            }
        }
        __syncthreads();
        #pragma unroll
        for (int k = 0; k < BK; k++) {
            float sf[4];
            #pragma unroll
            for (int i = 0; i < 4; i++) sf[i] = s_s[ty4 + i][k];
            const float4 f1 = *(const float4*)&d1_s[k][tx4];
            const float4 f2 = *(const float4*)&d2_s[k][tx4];
            #pragma unroll
            for (int i = 0; i < 4; i++) {
                acc1[i][0] += sf[i] * f1.x; acc1[i][1] += sf[i] * f1.y;
                acc1[i][2] += sf[i] * f1.z; acc1[i][3] += sf[i] * f1.w;
                acc2[i][0] += sf[i] * f2.x; acc2[i][1] += sf[i] * f2.y;
                acc2[i][2] += sf[i] * f2.z; acc2[i][3] += sf[i] * f2.w;
            }
        }
        __syncthreads();
    }

    // epilogue: apply column scales, store
    const int db = d0 + tx4;
    const float4 iv1 = *(const float4*)&inv1[db];
    const float4 iv2 = *(const float4*)&inv2[db];
    #pragma unroll
    for (int i = 0; i < 4; i++) {
        const int c = c0 + ty4 + i;
        float4 r1, r2;
        r1.x = acc1[i][0] * iv1.x; r1.y = acc1[i][1] * iv1.y;
        r1.z = acc1[i][2] * iv1.z; r1.w = acc1[i][3] * iv1.w;
        r2.x = acc2[i][0] * iv2.x; r2.y = acc2[i][1] * iv2.y;
        r2.z = acc2[i][2] * iv2.z; r2.w = acc2[i][3] * iv2.w;
        *(float4*)&g_S1[((size_t)(b * CH + c)) * CH + db] = r1;
        *(float4*)&g_S2[((size_t)(b * CH + c)) * CH + db] = r2;
    }
}

// ---------------------------------------------------------------------------
// Kernel 3: row softmax of S1 and S2 in place. grid = B*C rows, 256 threads.
// ---------------------------------------------------------------------------
__global__ __launch_bounds__(256) void softmax_kernel() {
    const int row = blockIdx.x;                  // b*C + c
    const int t = threadIdx.x;
    const int lane = t & 31, w = t >> 5;
    __shared__ float sh1[8], sh2[8];
    const size_t base = (size_t)row * CH;
    const float v1 = g_S1[base + t];
    const float v2 = g_S2[base + t];

    float m1 = v1, m2 = v2;
    #pragma unroll
    for (int o = 16; o; o >>= 1) {
        m1 = fmaxf(m1, __shfl_xor_sync(0xffffffffu, m1, o));
        m2 = fmaxf(m2, __shfl_xor_sync(0xffffffffu, m2, o));
    }
    if (lane == 0) { sh1[w] = m1; sh2[w] = m2; }
    __syncthreads();
    m1 = sh1[0]; m2 = sh2[0];
    #pragma unroll
    for (int i = 1; i < 8; i++) { m1 = fmaxf(m1, sh1[i]); m2 = fmaxf(m2, sh2[i]); }

    const float e1 = __expf(v1 - m1);
    const float e2 = __expf(v2 - m2);
    __syncthreads();

    float s1 = e1, s2 = e2;
    #pragma unroll
    for (int o = 16; o; o >>= 1) {
        s1 += __shfl_xor_sync(0xffffffffu, s1, o);
        s2 += __shfl_xor_sync(0xffffffffu, s2, o);
    }
    if (lane == 0) { sh1[w] = s1; sh2[w] = s2; }
    __syncthreads();
    s1 = 0.f; s2 = 0.f;
    #pragma unroll
    for (int i = 0; i < 8; i++) { s1 += sh1[i]; s2 += sh2[i]; }

    g_S1[base + t] = e1 / s1;
    g_S2[base + t] = e2 / s2;
}

// ---------------------------------------------------------------------------
// Kernel 4: Z = A1 @ X1 + A2 @ X2  (per batch, [256 x 4096], K=256),
// then transposed residual write: out[b, n*C + d] = Z[d,n] + x1[b,f] + x2[b,f].
// grid = (64 n-tiles, 4 d-tiles, B), 256 threads, 64x64 tile.
// ---------------------------------------------------------------------------
__global__ __launch_bounds__(256) void out_kernel(const float* __restrict__ x1,
                                                  const float* __restrict__ x2,
                                                  float* __restrict__ out) {
    __shared__ float smem_raw[2 * 64 * 36 + 2 * BK * 68];   // 35840 B
    float (*A1s)[36] = (float(*)[36])smem_raw;
    float (*A2s)[36] = (float(*)[36])(smem_raw + 64 * 36);
    float (*X1s)[68] = (float(*)[68])(smem_raw + 2 * 64 * 36);
    float (*X2s)[68] = (float(*)[68])(smem_raw + 2 * 64 * 36 + BK * 68);

    const int b  = blockIdx.z;
    const int d0 = blockIdx.y * 64;
    const int n0 = blockIdx.x * 64;
    const int t  = threadIdx.x;
    const int tx = t & 15, ty = t >> 4;
    const int ty4 = ty * 4, tx4 = tx * 4;

    const float* A1 = g_S1 + (size_t)b * CH * CH;
    const float* A2 = g_S2 + (size_t)b * CH * CH;
    const float* X1 = x1 + (size_t)b * CN;
    const float* X2 = x2 + (size_t)b * CN;

    float acc[4][4] = {};   // acc[i][j]: d = d0+ty4+i (output row c), n = n0+tx4+j

    for (int kk = 0; kk < CH; kk += BK) {
        #pragma unroll
        for (int u = 0; u < 2; u++) {
            const int v = t + u * 256;           // 0..511
            {   // A tiles: 64 rows (d) x 32 (k), natural layout
                const int r = v >> 3, kq = (v & 7) * 4;
                *(float4*)&A1s[r][kq] = *(const float4*)(A1 + (size_t)(d0 + r) * CH + kk + kq);
                *(float4*)&A2s[r][kq] = *(const float4*)(A2 + (size_t)(d0 + r) * CH + kk + kq);
            }
            {   // X tiles: 32 rows (k) x 64 (n), natural (already K-major)
                const int r = v >> 4, nq = (v & 15) * 4;
                *(float4*)&X1s[r][nq] = *(const float4*)(X1 + (size_t)(kk + r) * NPIX + n0 + nq);
                *(float4*)&X2s[r][nq] = *(const float4*)(X2 + (size_t)(kk + r) * NPIX + n0 + nq);
            }
        }
        __syncthreads();
        #pragma unroll
        for (int k = 0; k < BK; k++) {
            float a1[4], a2[4];
            #pragma unroll
            for (int i = 0; i < 4; i++) { a1[i] = A1s[ty4 + i][k]; a2[i] = A2s[ty4 + i][k]; }
            const float4 f1 = *(const float4*)&X1s[k][tx4];
            const float4 f2 = *(const float4*)&X2s[k][tx4];
            #pragma unroll
            for (int i = 0; i < 4; i++) {
                acc[i][0] += a1[i] * f1.x + a2[i] * f2.x;
                acc[i][1] += a1[i] * f1.y + a2[i] * f2.y;
                acc[i][2] += a1[i] * f1.z + a2[i] * f2.z;
                acc[i][3] += a1[i] * f1.w + a2[i] * f2.w;
            }
        }
        __syncthreads();
    }

    // Stage Z into smem (reuse tile space) and do the transposed residual write.
    float (*Zs)[65] = (float(*)[65])smem_raw;   // [n][d], 64*65 = 4160 floats
    #pragma unroll
    for (int i = 0; i < 4; i++)
        #pragma unroll
        for (int j = 0; j < 4; j++)
            Zs[tx4 + j][ty4 + i] = acc[i][j];
    __syncthreads();

    #pragma unroll
    for (int r = 0; r < 16; r++) {
        const int e = t + r * 256;               // 0..4095
        const int d = e & 63, n = e >> 6;
        const size_t f = (size_t)(n0 + n) * CH + d0 + d;   // out flat index within batch
        const size_t g = (size_t)b * CN + f;
        out[g] = Zs[n][d] + x1[g] + x2[g];
    }
}

// ---------------------------------------------------------------------------
extern "C" void kernel_launch(void* const* d_in, const int* in_sizes, int n_in,
                              void* d_out, int out_size) {
    (void)in_sizes; (void)n_in; (void)out_size;
    const float* x1 = (const float*)d_in[0];
    const float* x2 = (const float*)d_in[1];
    float* out = (float*)d_out;

    norms_kernel<<<BATCH * CH, 256>>>(x1, x2);
    gram_kernel<<<dim3(4, 4, BATCH), 256>>>(x1, x2);
    softmax_kernel<<<BATCH * CH, 256>>>();
    out_kernel<<<dim3(64, 4, BATCH), 256>>>(x1, x2, out);
}